// round 13
// baseline (speedup 1.0000x reference)
#include <cuda_runtime.h>
#include <cuda_bf16.h>
#include <cstdint>

// ============================================================================
// x(8,4096,768) fp32 -> int8 quant -> GEMM vs weight_t(768,768) int8 (promoted
// to int32/fp32 by harness; detected) -> int32 acc * 2e-4 + bias -> fp32 out.
// Legacy mma.sync path (compute_103 baseline PTX; tcgen05 unavailable).
// R13: rebalanced to measured pipe rates (tensor 0.32 us/col, dp4a 0.16):
//      tile 128x192 = 64 tensor cols (8 mma warps) + 128 dp4a cols (16 warps),
//      768 thr/CTA, TK=128 x 3 stages (132KB -> 1 CTA/SM), 1024 tiles ->
//      6.74 -> 7 waves (96.3%). 6 warps/SMSP for LDS-latency hiding.
// ============================================================================
static constexpr int N_TOK = 32768;
static constexpr int KDIM  = 768;
static constexpr int MDIM  = 768;

static constexpr int TM = 128;      // token tile
static constexpr int TNT = 64;      // tensor-warp cols
static constexpr int TND = 128;     // dp4a-warp cols
static constexpr int TN  = TNT + TND;              // 192
static constexpr int TK = 128;      // K bytes per stage
static constexpr int STAGES = 3;
static constexpr int KSTEPS = KDIM / TK;           // 6
static constexpr int TILES_M = MDIM / TN;          // 4
static constexpr int ROWPAD = 144;  // 128B data + 16B pad: conflict-free
static constexpr int A_TILE_BYTES  = TM * ROWPAD;            // 18432
static constexpr int B_TILE_BYTES  = TNT * ROWPAD;           // 9216
static constexpr int B2_TILE_BYTES = (TK / 4) * TND * 4;     // 16384
static constexpr int STAGE_BYTES = A_TILE_BYTES + B_TILE_BYTES + B2_TILE_BYTES; // 44032
static constexpr int SMEM_ALLOC  = STAGES * STAGE_BYTES;     // 132096 -> 1 CTA/SM

static constexpr int A_CHUNKS  = TM * (TK / 16);     // 1024
static constexpr int B_CHUNKS  = TNT * (TK / 16);    // 512
static constexpr int B2_CHUNKS = B2_TILE_BYTES / 16; // 1024
static constexpr int TOT_CHUNKS = A_CHUNKS + B_CHUNKS + B2_CHUNKS; // 2560

static constexpr int NTHREADS = 768;   // 8 tensor warps + 16 dp4a warps

// Scratch (__device__ globals: the allowed allocation-free path)
__device__ int8_t  g_xq[(size_t)N_TOK * KDIM];    // quantized activations [N,K]
__device__ int8_t  g_wb[(size_t)MDIM * KDIM];     // weight transposed [M,K]
__device__ uint8_t g_wb2[(size_t)TILES_M * (KDIM / 4) * TND * 4];  // dp4a B packed

// ============================================================================
// PTX helpers
// ============================================================================
__device__ __forceinline__ uint32_t smem_to_u32(const void* p) {
    uint32_t a;
    asm("{ .reg .u64 t; cvta.to.shared.u64 t, %1; cvt.u32.u64 %0, t; }" : "=r"(a) : "l"(p));
    return a;
}
__device__ __forceinline__ void cp_async16(uint32_t dst, const void* src) {
    asm volatile("cp.async.cg.shared.global [%0], [%1], 16;" :: "r"(dst), "l"(src));
}
#define CP_COMMIT() asm volatile("cp.async.commit_group;" ::: "memory")
#define CP_WAIT1()  asm volatile("cp.async.wait_group 1;" ::: "memory")

__device__ __forceinline__ void ldmatrix_x4(uint32_t* r, uint32_t addr) {
    asm volatile("ldmatrix.sync.aligned.m8n8.x4.shared.b16 {%0,%1,%2,%3}, [%4];"
                 : "=r"(r[0]), "=r"(r[1]), "=r"(r[2]), "=r"(r[3]) : "r"(addr));
}
__device__ __forceinline__ void mma_s8(int* c, const uint32_t* a, const uint32_t* b) {
    asm volatile(
        "mma.sync.aligned.m16n8k32.row.col.s32.s8.s8.s32 "
        "{%0,%1,%2,%3}, {%4,%5,%6,%7}, {%8,%9}, {%0,%1,%2,%3};"
        : "+r"(c[0]), "+r"(c[1]), "+r"(c[2]), "+r"(c[3])
        : "r"(a[0]), "r"(a[1]), "r"(a[2]), "r"(a[3]), "r"(b[0]), "r"(b[1]));
}
__device__ __forceinline__ void lds128(uint32_t* r, uint32_t addr) {
    asm volatile("ld.shared.v4.u32 {%0,%1,%2,%3}, [%4];"
                 : "=r"(r[0]), "=r"(r[1]), "=r"(r[2]), "=r"(r[3]) : "r"(addr));
}

// ============================================================================
// Kernel 1: quantize x -> int8. q = clamp(rne(x*50), -128, 127). MLP=8.
// ============================================================================
__global__ __launch_bounds__(256) void quant_kernel(const float* __restrict__ x) {
    const int base = blockIdx.x * 2048 + threadIdx.x;
    const float4* xv = reinterpret_cast<const float4*>(x);
    float4 v[8];
#pragma unroll
    for (int k = 0; k < 8; ++k) v[k] = xv[base + k * 256];
#pragma unroll
    for (int k = 0; k < 8; ++k) {
        int q0 = min(max(__float2int_rn(v[k].x * 50.0f), -128), 127);
        int q1 = min(max(__float2int_rn(v[k].y * 50.0f), -128), 127);
        int q2 = min(max(__float2int_rn(v[k].z * 50.0f), -128), 127);
        int q3 = min(max(__float2int_rn(v[k].w * 50.0f), -128), 127);
        uint32_t lo = __byte_perm((uint32_t)q0, (uint32_t)q1, 0x4040);
        uint32_t hi = __byte_perm((uint32_t)q2, (uint32_t)q3, 0x4040);
        reinterpret_cast<uint32_t*>(g_xq)[base + k * 256] = __byte_perm(lo, hi, 0x5410);
    }
}

// ============================================================================
// dtype detection helper (harness promotes int8 tensors to int32/fp32)
// ============================================================================
__device__ __forceinline__ int detect_mode(const void* w) {
    const int32_t* wi = (const int32_t*)w;
    const float*   wf = (const float*)w;
    bool ok32 = true, okf = true;
    for (int i = threadIdx.x; i < 1024; i += blockDim.x) {
        int32_t a = wi[i];
        ok32 &= (a >= -128 && a <= 127);
        float f = wf[i];
        okf  &= (f == rintf(f) && f >= -128.f && f <= 127.f);
    }
    ok32 = __syncthreads_and(ok32);
    okf  = __syncthreads_and(okf);
    return ok32 ? 1 : (okf ? 2 : 0);
}
__device__ __forceinline__ int8_t read_w(const void* w, size_t idx, int mode) {
    if (mode == 1) return (int8_t)((const int32_t*)w)[idx];
    if (mode == 2) return (int8_t)(int)((const float*)w)[idx];
    return ((const int8_t*)w)[idx];
}

// ============================================================================
// Kernel 2: transpose weight [K,M] -> [M,K] int8 (tensor-warp operand)
// ============================================================================
__global__ __launch_bounds__(256) void wtrans_kernel(const void* __restrict__ wsrc) {
    __shared__ int8_t t[32][33];
    const int mode = detect_mode(wsrc);
    const int kb = blockIdx.x * 32, mb = blockIdx.y * 32;
    const int tx = threadIdx.x & 31, ty = threadIdx.x >> 5;
#pragma unroll
    for (int i = 0; i < 4; ++i) {
        int r = ty + i * 8;
        t[r][tx] = read_w(wsrc, (size_t)(kb + r) * MDIM + mb + tx, mode);
    }
    __syncthreads();
#pragma unroll
    for (int i = 0; i < 4; ++i) {
        int r = ty + i * 8;
        g_wb[(size_t)(mb + r) * KDIM + kb + tx] = t[tx][r];
    }
}

// ============================================================================
// Kernel 2b: pack dp4a B: g_wb2[mblk][kc][col] = w[4kc..4kc+3][mblk*192+64+col]
// ============================================================================
__global__ __launch_bounds__(256) void wpack2_kernel(const void* __restrict__ wsrc) {
    const int mode = detect_mode(wsrc);
    const int t = blockIdx.x * 256 + threadIdx.x;     // over 4*192*128 = 98304
    if (t >= TILES_M * (KDIM / 4) * TND) return;
    const int mb  = t / ((KDIM / 4) * TND);
    const int rem = t - mb * ((KDIM / 4) * TND);
    const int kc  = rem / TND;
    const int col = rem - kc * TND;
    const int m = mb * TN + TNT + col;
    uint32_t p = 0;
#pragma unroll
    for (int j = 0; j < 4; ++j) {
        int8_t b = read_w(wsrc, (size_t)(kc * 4 + j) * MDIM + m, mode);
        p |= (uint32_t)(uint8_t)b << (j * 8);
    }
    reinterpret_cast<uint32_t*>(g_wb2)[t] = p;
}

// ============================================================================
// Kernel 3: hybrid GEMM. CTA tile 128x192, 768 threads:
//   warps 0-7  : mma path, cols [0,64): warp tile 32 rows x 32 cols
//   warps 8-23 : dp4a path, cols [64,192): warp = (32-row slab, 32-col quarter)
// TK=128, 3-stage ring, 6 barriers per tile.
// ============================================================================
__global__ __launch_bounds__(NTHREADS, 1)
void gemm_kernel(const float* __restrict__ bias, float* __restrict__ out) {
    extern __shared__ char smem[];
    const uint32_t sbase = smem_to_u32(smem);
    const int tid  = threadIdx.x;
    const int lane = tid & 31;
    const int warp = tid >> 5;
    const int m0 = blockIdx.x * TN;    // 4 column tiles
    const int n0 = blockIdx.y * TM;    // 256 token tiles
    const int mblk = blockIdx.x;

    auto load_stage = [&](int s) {
        const int buf = s % STAGES;
        const uint32_t sa  = sbase + buf * STAGE_BYTES;
        const uint32_t sb  = sa + A_TILE_BYTES;
        const uint32_t sb2 = sb + B_TILE_BYTES;
        const int k0 = s * TK;
#pragma unroll
        for (int it = 0; it < 4; ++it) {
            int g = tid + it * NTHREADS;          // 0..3071; active < 2560
            if (g < A_CHUNKS) {
                int row = g >> 3, c = g & 7;      // 8 chunks per 128B row
                cp_async16(sa + row * ROWPAD + c * 16,
                           g_xq + (size_t)(n0 + row) * KDIM + k0 + c * 16);
            } else if (g < A_CHUNKS + B_CHUNKS) {
                int h = g - A_CHUNKS;
                int row = h >> 3, c = h & 7;
                cp_async16(sb + row * ROWPAD + c * 16,
                           g_wb + (size_t)(m0 + row) * KDIM + k0 + c * 16);
            } else if (g < TOT_CHUNKS) {
                int h = g - A_CHUNKS - B_CHUNKS;  // 0..1023
                cp_async16(sb2 + h * 16,
                           g_wb2 + (size_t)mblk * (KDIM / 4) * TND * 4
                                 + (size_t)(k0 / 4) * TND * 4 + h * 16);
            }
        }
    };

    load_stage(0); CP_COMMIT();
    load_stage(1); CP_COMMIT();

    const float eff = (float)(0.02 * 0.01);

    if (warp < 8) {
        // ================== tensor path: 64 cols ==================
        const int wm = warp >> 1;          // 0..3 : 32-token slab
        const int wn = warp & 1;           // 0..1 : 32-col half
        int acc[2][4][4];
#pragma unroll
        for (int i = 0; i < 2; ++i)
#pragma unroll
            for (int j = 0; j < 4; ++j)
#pragma unroll
                for (int k = 0; k < 4; ++k) acc[i][j][k] = 0;

        const int a_row = (lane & 7) + ((lane >> 3) & 1) * 8;
        const int a_kb  = (lane >> 4) * 16;
        const int b_row = lane & 7;
        const int b_grp = (lane >> 4) & 1;
        const int b_kb  = ((lane >> 3) & 1) * 16;

        for (int s = 0; s < KSTEPS; ++s) {
            CP_WAIT1();
            __syncthreads();
            if (s + 2 < KSTEPS) load_stage(s + 2);
            CP_COMMIT();
            const int buf = s % STAGES;
            const uint32_t sa = sbase + buf * STAGE_BYTES;
            const uint32_t sb = sa + A_TILE_BYTES;
#pragma unroll
            for (int kk = 0; kk < 4; ++kk) {   // four k32 steps per 128B stage
                uint32_t afrag[2][4], bfrag[4][2];
                const uint32_t abase =
                    sa + (uint32_t)(wm * 32 + a_row) * ROWPAD + kk * 32 + a_kb;
#pragma unroll
                for (int mf = 0; mf < 2; ++mf)
                    ldmatrix_x4(afrag[mf], abase + (uint32_t)mf * 16 * ROWPAD);
                const uint32_t bbase =
                    sb + (uint32_t)(wn * 32 + b_grp * 8 + b_row) * ROWPAD + kk * 32 + b_kb;
#pragma unroll
                for (int np = 0; np < 2; ++np) {
                    uint32_t r[4];
                    ldmatrix_x4(r, bbase + (uint32_t)np * 16 * ROWPAD);
                    bfrag[np * 2 + 0][0] = r[0];
                    bfrag[np * 2 + 0][1] = r[1];
                    bfrag[np * 2 + 1][0] = r[2];
                    bfrag[np * 2 + 1][1] = r[3];
                }
#pragma unroll
                for (int mf = 0; mf < 2; ++mf)
#pragma unroll
                    for (int nf = 0; nf < 4; ++nf)
                        mma_s8(acc[mf][nf], afrag[mf], bfrag[nf]);
            }
        }
        // epilogue
        float2 bv[4];
#pragma unroll
        for (int nf = 0; nf < 4; ++nf) {
            const int col = m0 + wn * 32 + nf * 8 + 2 * (lane & 3);
            bv[nf].x = __ldg(bias + col);
            bv[nf].y = __ldg(bias + col + 1);
        }
#pragma unroll
        for (int mf = 0; mf < 2; ++mf) {
            const int row_lo = n0 + wm * 32 + mf * 16 + (lane >> 2);
            float* p_lo = out + (size_t)row_lo * MDIM;
            float* p_hi = p_lo + 8 * MDIM;
#pragma unroll
            for (int nf = 0; nf < 4; ++nf) {
                const int col = m0 + wn * 32 + nf * 8 + 2 * (lane & 3);
                float2 lo, hi;
                lo.x = (float)acc[mf][nf][0] * eff + bv[nf].x;
                lo.y = (float)acc[mf][nf][1] * eff + bv[nf].y;
                hi.x = (float)acc[mf][nf][2] * eff + bv[nf].x;
                hi.y = (float)acc[mf][nf][3] * eff + bv[nf].y;
                *reinterpret_cast<float2*>(p_lo + col) = lo;
                *reinterpret_cast<float2*>(p_hi + col) = hi;
            }
        }
    } else {
        // ================== dp4a path: 128 cols on the IMAD pipe ==================
        const int w  = warp - 8;          // 0..15
        const int rs = w & 3;             // 32-row slab
        const int ch = w >> 2;            // 0..3 : 32-col quarter
        const int rg = lane >> 2;         // 0..7 : 4-row group
        const int cg = lane & 3;          // 0..3 : 8-col group
        int dacc[4][8];
#pragma unroll
        for (int i = 0; i < 4; ++i)
#pragma unroll
            for (int j = 0; j < 8; ++j) dacc[i][j] = 0;

        const uint32_t arow0 = (uint32_t)(rs * 32 + rg * 4);
        const uint32_t bcol0 = (uint32_t)(ch * 32 + cg * 8);

        for (int s = 0; s < KSTEPS; ++s) {
            CP_WAIT1();
            __syncthreads();
            if (s + 2 < KSTEPS) load_stage(s + 2);
            CP_COMMIT();
            const int buf = s % STAGES;
            const uint32_t sa  = sbase + buf * STAGE_BYTES;
            const uint32_t sb2 = sa + A_TILE_BYTES + B_TILE_BYTES;
#pragma unroll
            for (int kk = 0; kk < 4; ++kk) {
#pragma unroll
                for (int h = 0; h < 2; ++h) {      // k16 halves
                    uint32_t a[4][4];
#pragma unroll
                    for (int i = 0; i < 4; ++i)
                        lds128(a[i], sa + (arow0 + i) * ROWPAD + kk * 32 + h * 16);
#pragma unroll
                    for (int c = 0; c < 4; ++c) {  // 4 k-chunks in this half
                        const uint32_t boff =
                            sb2 + (uint32_t)(((kk * 8 + h * 4 + c) * TND + bcol0) * 4);
                        uint32_t b[8];
                        lds128(b, boff);
                        lds128(b + 4, boff + 16);
#pragma unroll
                        for (int i = 0; i < 4; ++i)
#pragma unroll
                            for (int j = 0; j < 8; ++j)
                                dacc[i][j] = __dp4a((int)a[i][c], (int)b[j], dacc[i][j]);
                    }
                }
            }
        }
        // epilogue
        const int bcol = m0 + TNT + (int)bcol0;
        float bb[8];
#pragma unroll
        for (int j = 0; j < 8; ++j) bb[j] = __ldg(bias + bcol + j);
#pragma unroll
        for (int i = 0; i < 4; ++i) {
            const int row = n0 + (int)arow0 + i;
            float* p = out + (size_t)row * MDIM + bcol;
            float4 v0, v1;
            v0.x = (float)dacc[i][0] * eff + bb[0];
            v0.y = (float)dacc[i][1] * eff + bb[1];
            v0.z = (float)dacc[i][2] * eff + bb[2];
            v0.w = (float)dacc[i][3] * eff + bb[3];
            v1.x = (float)dacc[i][4] * eff + bb[4];
            v1.y = (float)dacc[i][5] * eff + bb[5];
            v1.z = (float)dacc[i][6] * eff + bb[6];
            v1.w = (float)dacc[i][7] * eff + bb[7];
            *reinterpret_cast<float4*>(p) = v0;
            *reinterpret_cast<float4*>(p + 4) = v1;
        }
    }
}

// ============================================================================
// Launch
// ============================================================================
extern "C" void kernel_launch(void* const* d_in, const int* in_sizes, int n_in,
                              void* d_out, int out_size) {
    const float* x    = (const float*)d_in[0];
    const void*  wt   = d_in[1];
    const float* bias = (const float*)d_in[2];
    float*       out  = (float*)d_out;

    cudaFuncSetAttribute(gemm_kernel, cudaFuncAttributeMaxDynamicSharedMemorySize,
                         SMEM_ALLOC);

    {
        int nblk = (N_TOK * KDIM) / 4 / 2048;   // 3072 blocks
        quant_kernel<<<nblk, 256>>>(x);
    }
    {
        dim3 grid(KDIM / 32, MDIM / 32);
        wtrans_kernel<<<grid, 256>>>(wt);
    }
    {
        int n = TILES_M * (KDIM / 4) * TND;     // 98304
        wpack2_kernel<<<(n + 255) / 256, 256>>>(wt);
    }
    {
        dim3 grid(MDIM / TN, N_TOK / TM);       // (4, 256) = 1024 tiles
        gemm_kernel<<<grid, NTHREADS, SMEM_ALLOC>>>(bias, out);
    }
    (void)in_sizes; (void)n_in; (void)out_size;
}

// round 14
// speedup vs baseline: 1.0597x; 1.0597x over previous
#include <cuda_runtime.h>
#include <cuda_bf16.h>
#include <cstdint>

// ============================================================================
// x(8,4096,768) fp32 -> int8 quant -> GEMM vs weight_t(768,768) int8 (promoted
// to int32/fp32 by harness; detected) -> int32 acc * 2e-4 + bias -> fp32 out.
// Legacy mma.sync path (compute_103 baseline PTX; tcgen05 unavailable).
// R14: rate-matched split at 2 CTA/SM. Tile 128x96 = 32 tensor cols (4 mma
//      warps, 32x32 each) + 64 dp4a cols (8 warps). 384 thr/CTA, TK=128 x 3
//      stages (93.7KB -> 2 CTA/SM, 24 warps/SM). 2048 tiles -> 7 waves 96.3%.
//      Cross-CTA interleave restores pipe duty that R13's fat 1-CTA lost.
// ============================================================================
static constexpr int N_TOK = 32768;
static constexpr int KDIM  = 768;
static constexpr int MDIM  = 768;

static constexpr int TM = 128;      // token tile
static constexpr int TNT = 32;      // tensor-warp cols
static constexpr int TND = 64;      // dp4a-warp cols
static constexpr int TN  = TNT + TND;              // 96
static constexpr int TK = 128;      // K bytes per stage
static constexpr int STAGES = 3;
static constexpr int KSTEPS = KDIM / TK;           // 6
static constexpr int TILES_M = MDIM / TN;          // 8
static constexpr int ROWPAD = 144;  // 128B data + 16B pad: conflict-free
static constexpr int A_TILE_BYTES  = TM * ROWPAD;            // 18432
static constexpr int B_TILE_BYTES  = TNT * ROWPAD;           // 4608
static constexpr int B2_TILE_BYTES = (TK / 4) * TND * 4;     // 8192
static constexpr int STAGE_BYTES = A_TILE_BYTES + B_TILE_BYTES + B2_TILE_BYTES; // 31232
static constexpr int SMEM_ALLOC  = STAGES * STAGE_BYTES;     // 93696 -> 2 CTA/SM

static constexpr int A_CHUNKS  = TM * (TK / 16);     // 1024
static constexpr int B_CHUNKS  = TNT * (TK / 16);    // 256
static constexpr int B2_CHUNKS = B2_TILE_BYTES / 16; // 512
static constexpr int TOT_CHUNKS = A_CHUNKS + B_CHUNKS + B2_CHUNKS; // 1792

static constexpr int NTHREADS = 384;   // 4 tensor warps + 8 dp4a warps

// Scratch (__device__ globals: the allowed allocation-free path)
__device__ int8_t  g_xq[(size_t)N_TOK * KDIM];    // quantized activations [N,K]
__device__ int8_t  g_wb[(size_t)MDIM * KDIM];     // weight transposed [M,K]
__device__ uint8_t g_wb2[(size_t)TILES_M * (KDIM / 4) * TND * 4];  // dp4a B packed

// ============================================================================
// PTX helpers
// ============================================================================
__device__ __forceinline__ uint32_t smem_to_u32(const void* p) {
    uint32_t a;
    asm("{ .reg .u64 t; cvta.to.shared.u64 t, %1; cvt.u32.u64 %0, t; }" : "=r"(a) : "l"(p));
    return a;
}
__device__ __forceinline__ void cp_async16(uint32_t dst, const void* src) {
    asm volatile("cp.async.cg.shared.global [%0], [%1], 16;" :: "r"(dst), "l"(src));
}
#define CP_COMMIT() asm volatile("cp.async.commit_group;" ::: "memory")
#define CP_WAIT1()  asm volatile("cp.async.wait_group 1;" ::: "memory")

__device__ __forceinline__ void ldmatrix_x4(uint32_t* r, uint32_t addr) {
    asm volatile("ldmatrix.sync.aligned.m8n8.x4.shared.b16 {%0,%1,%2,%3}, [%4];"
                 : "=r"(r[0]), "=r"(r[1]), "=r"(r[2]), "=r"(r[3]) : "r"(addr));
}
__device__ __forceinline__ void mma_s8(int* c, const uint32_t* a, const uint32_t* b) {
    asm volatile(
        "mma.sync.aligned.m16n8k32.row.col.s32.s8.s8.s32 "
        "{%0,%1,%2,%3}, {%4,%5,%6,%7}, {%8,%9}, {%0,%1,%2,%3};"
        : "+r"(c[0]), "+r"(c[1]), "+r"(c[2]), "+r"(c[3])
        : "r"(a[0]), "r"(a[1]), "r"(a[2]), "r"(a[3]), "r"(b[0]), "r"(b[1]));
}
__device__ __forceinline__ void lds128(uint32_t* r, uint32_t addr) {
    asm volatile("ld.shared.v4.u32 {%0,%1,%2,%3}, [%4];"
                 : "=r"(r[0]), "=r"(r[1]), "=r"(r[2]), "=r"(r[3]) : "r"(addr));
}

// ============================================================================
// Kernel 1: quantize x -> int8. q = clamp(rne(x*50), -128, 127). MLP=8.
// ============================================================================
__global__ __launch_bounds__(256) void quant_kernel(const float* __restrict__ x) {
    const int base = blockIdx.x * 2048 + threadIdx.x;
    const float4* xv = reinterpret_cast<const float4*>(x);
    float4 v[8];
#pragma unroll
    for (int k = 0; k < 8; ++k) v[k] = xv[base + k * 256];
#pragma unroll
    for (int k = 0; k < 8; ++k) {
        int q0 = min(max(__float2int_rn(v[k].x * 50.0f), -128), 127);
        int q1 = min(max(__float2int_rn(v[k].y * 50.0f), -128), 127);
        int q2 = min(max(__float2int_rn(v[k].z * 50.0f), -128), 127);
        int q3 = min(max(__float2int_rn(v[k].w * 50.0f), -128), 127);
        uint32_t lo = __byte_perm((uint32_t)q0, (uint32_t)q1, 0x4040);
        uint32_t hi = __byte_perm((uint32_t)q2, (uint32_t)q3, 0x4040);
        reinterpret_cast<uint32_t*>(g_xq)[base + k * 256] = __byte_perm(lo, hi, 0x5410);
    }
}

// ============================================================================
// dtype detection helper (harness promotes int8 tensors to int32/fp32)
// ============================================================================
__device__ __forceinline__ int detect_mode(const void* w) {
    const int32_t* wi = (const int32_t*)w;
    const float*   wf = (const float*)w;
    bool ok32 = true, okf = true;
    for (int i = threadIdx.x; i < 1024; i += blockDim.x) {
        int32_t a = wi[i];
        ok32 &= (a >= -128 && a <= 127);
        float f = wf[i];
        okf  &= (f == rintf(f) && f >= -128.f && f <= 127.f);
    }
    ok32 = __syncthreads_and(ok32);
    okf  = __syncthreads_and(okf);
    return ok32 ? 1 : (okf ? 2 : 0);
}
__device__ __forceinline__ int8_t read_w(const void* w, size_t idx, int mode) {
    if (mode == 1) return (int8_t)((const int32_t*)w)[idx];
    if (mode == 2) return (int8_t)(int)((const float*)w)[idx];
    return ((const int8_t*)w)[idx];
}

// ============================================================================
// Kernel 2: transpose weight [K,M] -> [M,K] int8 (tensor-warp operand)
// ============================================================================
__global__ __launch_bounds__(256) void wtrans_kernel(const void* __restrict__ wsrc) {
    __shared__ int8_t t[32][33];
    const int mode = detect_mode(wsrc);
    const int kb = blockIdx.x * 32, mb = blockIdx.y * 32;
    const int tx = threadIdx.x & 31, ty = threadIdx.x >> 5;
#pragma unroll
    for (int i = 0; i < 4; ++i) {
        int r = ty + i * 8;
        t[r][tx] = read_w(wsrc, (size_t)(kb + r) * MDIM + mb + tx, mode);
    }
    __syncthreads();
#pragma unroll
    for (int i = 0; i < 4; ++i) {
        int r = ty + i * 8;
        g_wb[(size_t)(mb + r) * KDIM + kb + tx] = t[tx][r];
    }
}

// ============================================================================
// Kernel 2b: pack dp4a B: g_wb2[mblk][kc][col] = w[4kc..4kc+3][mblk*96+32+col]
// ============================================================================
__global__ __launch_bounds__(256) void wpack2_kernel(const void* __restrict__ wsrc) {
    const int mode = detect_mode(wsrc);
    const int t = blockIdx.x * 256 + threadIdx.x;     // over 8*192*64 = 98304
    if (t >= TILES_M * (KDIM / 4) * TND) return;
    const int mb  = t / ((KDIM / 4) * TND);
    const int rem = t - mb * ((KDIM / 4) * TND);
    const int kc  = rem / TND;
    const int col = rem - kc * TND;
    const int m = mb * TN + TNT + col;
    uint32_t p = 0;
#pragma unroll
    for (int j = 0; j < 4; ++j) {
        int8_t b = read_w(wsrc, (size_t)(kc * 4 + j) * MDIM + m, mode);
        p |= (uint32_t)(uint8_t)b << (j * 8);
    }
    reinterpret_cast<uint32_t*>(g_wb2)[t] = p;
}

// ============================================================================
// Kernel 3: hybrid GEMM. CTA tile 128x96, 384 threads, 2 CTA/SM:
//   warps 0-3 : mma path, cols [0,32): warp = 32-row slab x 32 cols
//   warps 4-11: dp4a path, cols [32,96): warp = (32-row slab, 32-col half)
// TK=128, 3-stage ring, 6 barriers per tile.
// ============================================================================
__global__ __launch_bounds__(NTHREADS, 2)
void gemm_kernel(const float* __restrict__ bias, float* __restrict__ out) {
    extern __shared__ char smem[];
    const uint32_t sbase = smem_to_u32(smem);
    const int tid  = threadIdx.x;
    const int lane = tid & 31;
    const int warp = tid >> 5;
    const int m0 = blockIdx.x * TN;    // 8 column tiles
    const int n0 = blockIdx.y * TM;    // 256 token tiles
    const int mblk = blockIdx.x;

    auto load_stage = [&](int s) {
        const int buf = s % STAGES;
        const uint32_t sa  = sbase + buf * STAGE_BYTES;
        const uint32_t sb  = sa + A_TILE_BYTES;
        const uint32_t sb2 = sb + B_TILE_BYTES;
        const int k0 = s * TK;
#pragma unroll
        for (int it = 0; it < 5; ++it) {
            int g = tid + it * NTHREADS;          // 0..1919; active < 1792
            if (g < A_CHUNKS) {
                int row = g >> 3, c = g & 7;      // 8 chunks per 128B row
                cp_async16(sa + row * ROWPAD + c * 16,
                           g_xq + (size_t)(n0 + row) * KDIM + k0 + c * 16);
            } else if (g < A_CHUNKS + B_CHUNKS) {
                int h = g - A_CHUNKS;             // 0..255
                int row = h >> 3, c = h & 7;
                cp_async16(sb + row * ROWPAD + c * 16,
                           g_wb + (size_t)(m0 + row) * KDIM + k0 + c * 16);
            } else if (g < TOT_CHUNKS) {
                int h = g - A_CHUNKS - B_CHUNKS;  // 0..511
                cp_async16(sb2 + h * 16,
                           g_wb2 + (size_t)mblk * (KDIM / 4) * TND * 4
                                 + (size_t)(k0 / 4) * TND * 4 + h * 16);
            }
        }
    };

    load_stage(0); CP_COMMIT();
    load_stage(1); CP_COMMIT();

    const float eff = (float)(0.02 * 0.01);

    if (warp < 4) {
        // ================== tensor path: 32 cols, warp = 32-row slab ==================
        const int wm = warp;               // 0..3
        int acc[2][4][4];
#pragma unroll
        for (int i = 0; i < 2; ++i)
#pragma unroll
            for (int j = 0; j < 4; ++j)
#pragma unroll
                for (int k = 0; k < 4; ++k) acc[i][j][k] = 0;

        const int a_row = (lane & 7) + ((lane >> 3) & 1) * 8;
        const int a_kb  = (lane >> 4) * 16;
        const int b_row = lane & 7;
        const int b_grp = (lane >> 4) & 1;
        const int b_kb  = ((lane >> 3) & 1) * 16;

        for (int s = 0; s < KSTEPS; ++s) {
            CP_WAIT1();
            __syncthreads();
            if (s + 2 < KSTEPS) load_stage(s + 2);
            CP_COMMIT();
            const int buf = s % STAGES;
            const uint32_t sa = sbase + buf * STAGE_BYTES;
            const uint32_t sb = sa + A_TILE_BYTES;
#pragma unroll
            for (int kk = 0; kk < 4; ++kk) {   // four k32 steps per 128B stage
                uint32_t afrag[2][4], bfrag[4][2];
                const uint32_t abase =
                    sa + (uint32_t)(wm * 32 + a_row) * ROWPAD + kk * 32 + a_kb;
#pragma unroll
                for (int mf = 0; mf < 2; ++mf)
                    ldmatrix_x4(afrag[mf], abase + (uint32_t)mf * 16 * ROWPAD);
                const uint32_t bbase =
                    sb + (uint32_t)(b_grp * 8 + b_row) * ROWPAD + kk * 32 + b_kb;
#pragma unroll
                for (int np = 0; np < 2; ++np) {
                    uint32_t r[4];
                    ldmatrix_x4(r, bbase + (uint32_t)np * 16 * ROWPAD);
                    bfrag[np * 2 + 0][0] = r[0];
                    bfrag[np * 2 + 0][1] = r[1];
                    bfrag[np * 2 + 1][0] = r[2];
                    bfrag[np * 2 + 1][1] = r[3];
                }
#pragma unroll
                for (int mf = 0; mf < 2; ++mf)
#pragma unroll
                    for (int nf = 0; nf < 4; ++nf)
                        mma_s8(acc[mf][nf], afrag[mf], bfrag[nf]);
            }
        }
        // epilogue
        float2 bv[4];
#pragma unroll
        for (int nf = 0; nf < 4; ++nf) {
            const int col = m0 + nf * 8 + 2 * (lane & 3);
            bv[nf].x = __ldg(bias + col);
            bv[nf].y = __ldg(bias + col + 1);
        }
#pragma unroll
        for (int mf = 0; mf < 2; ++mf) {
            const int row_lo = n0 + wm * 32 + mf * 16 + (lane >> 2);
            float* p_lo = out + (size_t)row_lo * MDIM;
            float* p_hi = p_lo + 8 * MDIM;
#pragma unroll
            for (int nf = 0; nf < 4; ++nf) {
                const int col = m0 + nf * 8 + 2 * (lane & 3);
                float2 lo, hi;
                lo.x = (float)acc[mf][nf][0] * eff + bv[nf].x;
                lo.y = (float)acc[mf][nf][1] * eff + bv[nf].y;
                hi.x = (float)acc[mf][nf][2] * eff + bv[nf].x;
                hi.y = (float)acc[mf][nf][3] * eff + bv[nf].y;
                *reinterpret_cast<float2*>(p_lo + col) = lo;
                *reinterpret_cast<float2*>(p_hi + col) = hi;
            }
        }
    } else {
        // ================== dp4a path: 64 cols on the IMAD pipe ==================
        const int w  = warp - 4;          // 0..7
        const int rs = w & 3;             // 32-row slab
        const int ch = w >> 2;            // 0..1 : 32-col half
        const int rg = lane >> 2;         // 0..7 : 4-row group
        const int cg = lane & 3;          // 0..3 : 8-col group
        int dacc[4][8];
#pragma unroll
        for (int i = 0; i < 4; ++i)
#pragma unroll
            for (int j = 0; j < 8; ++j) dacc[i][j] = 0;

        const uint32_t arow0 = (uint32_t)(rs * 32 + rg * 4);
        const uint32_t bcol0 = (uint32_t)(ch * 32 + cg * 8);

        for (int s = 0; s < KSTEPS; ++s) {
            CP_WAIT1();
            __syncthreads();
            if (s + 2 < KSTEPS) load_stage(s + 2);
            CP_COMMIT();
            const int buf = s % STAGES;
            const uint32_t sa  = sbase + buf * STAGE_BYTES;
            const uint32_t sb2 = sa + A_TILE_BYTES + B_TILE_BYTES;
#pragma unroll
            for (int kk = 0; kk < 4; ++kk) {
#pragma unroll
                for (int h = 0; h < 2; ++h) {      // k16 halves
                    uint32_t a[4][4];
#pragma unroll
                    for (int i = 0; i < 4; ++i)
                        lds128(a[i], sa + (arow0 + i) * ROWPAD + kk * 32 + h * 16);
#pragma unroll
                    for (int c = 0; c < 4; ++c) {  // 4 k-chunks in this half
                        const uint32_t boff =
                            sb2 + (uint32_t)(((kk * 8 + h * 4 + c) * TND + bcol0) * 4);
                        uint32_t b[8];
                        lds128(b, boff);
                        lds128(b + 4, boff + 16);
#pragma unroll
                        for (int i = 0; i < 4; ++i)
#pragma unroll
                            for (int j = 0; j < 8; ++j)
                                dacc[i][j] = __dp4a((int)a[i][c], (int)b[j], dacc[i][j]);
                    }
                }
            }
        }
        // epilogue
        const int bcol = m0 + TNT + (int)bcol0;
        float bb[8];
#pragma unroll
        for (int j = 0; j < 8; ++j) bb[j] = __ldg(bias + bcol + j);
#pragma unroll
        for (int i = 0; i < 4; ++i) {
            const int row = n0 + (int)arow0 + i;
            float* p = out + (size_t)row * MDIM + bcol;
            float4 v0, v1;
            v0.x = (float)dacc[i][0] * eff + bb[0];
            v0.y = (float)dacc[i][1] * eff + bb[1];
            v0.z = (float)dacc[i][2] * eff + bb[2];
            v0.w = (float)dacc[i][3] * eff + bb[3];
            v1.x = (float)dacc[i][4] * eff + bb[4];
            v1.y = (float)dacc[i][5] * eff + bb[5];
            v1.z = (float)dacc[i][6] * eff + bb[6];
            v1.w = (float)dacc[i][7] * eff + bb[7];
            *reinterpret_cast<float4*>(p) = v0;
            *reinterpret_cast<float4*>(p + 4) = v1;
        }
    }
}

// ============================================================================
// Launch
// ============================================================================
extern "C" void kernel_launch(void* const* d_in, const int* in_sizes, int n_in,
                              void* d_out, int out_size) {
    const float* x    = (const float*)d_in[0];
    const void*  wt   = d_in[1];
    const float* bias = (const float*)d_in[2];
    float*       out  = (float*)d_out;

    cudaFuncSetAttribute(gemm_kernel, cudaFuncAttributeMaxDynamicSharedMemorySize,
                         SMEM_ALLOC);

    {
        int nblk = (N_TOK * KDIM) / 4 / 2048;   // 3072 blocks
        quant_kernel<<<nblk, 256>>>(x);
    }
    {
        dim3 grid(KDIM / 32, MDIM / 32);
        wtrans_kernel<<<grid, 256>>>(wt);
    }
    {
        int n = TILES_M * (KDIM / 4) * TND;     // 98304
        wpack2_kernel<<<(n + 255) / 256, 256>>>(wt);
    }
    {
        dim3 grid(MDIM / TN, N_TOK / TM);       // (8, 256) = 2048 tiles
        gemm_kernel<<<grid, NTHREADS, SMEM_ALLOC>>>(bias, out);
    }
    (void)in_sizes; (void)n_in; (void)out_size;
}

// round 15
// speedup vs baseline: 1.1511x; 1.0863x over previous
#include <cuda_runtime.h>
#include <cuda_bf16.h>
#include <cstdint>

// ============================================================================
// x(8,4096,768) fp32 -> int8 quant -> GEMM vs weight_t(768,768) int8 (promoted
// to int32/fp32 by harness; detected) -> int32 acc * 2e-4 + bias -> fp32 out.
// Legacy mma.sync path (compute_103 baseline PTX; tcgen05 unavailable).
// R15: R12's balanced split (TNT=64 / TND=64, 8+8 warps) at 2 CTA/SM.
//      Duty laws measured R10-R14: tensor needs 4 warps/SMSP for ~82% duty;
//      dp4a adds ~10-16%/warp/SMSP. 2 CTA x 512thr = 4+4 per SMSP.
//      Register-slimmed (<64/thread): dp4a 'a' via lds32 (4 live regs),
//      inline bias. TK=128 x 3 stages = 107.5KB/CTA -> 2 CTA/SM.
// ============================================================================
static constexpr int N_TOK = 32768;
static constexpr int KDIM  = 768;
static constexpr int MDIM  = 768;

static constexpr int TM = 128;      // token tile
static constexpr int TNT = 64;      // tensor-warp cols
static constexpr int TND = 64;      // dp4a-warp cols
static constexpr int TN  = TNT + TND;              // 128
static constexpr int TK = 128;      // K bytes per stage
static constexpr int STAGES = 3;
static constexpr int KSTEPS = KDIM / TK;           // 6
static constexpr int TILES_M = MDIM / TN;          // 6
static constexpr int ROWPAD = 144;  // 128B data + 16B pad: conflict-free
static constexpr int A_TILE_BYTES  = TM * ROWPAD;            // 18432
static constexpr int B_TILE_BYTES  = TNT * ROWPAD;           // 9216
static constexpr int B2_TILE_BYTES = (TK / 4) * TND * 4;     // 8192
static constexpr int STAGE_BYTES = A_TILE_BYTES + B_TILE_BYTES + B2_TILE_BYTES; // 35840
static constexpr int SMEM_ALLOC  = STAGES * STAGE_BYTES;     // 107520 -> 2 CTA/SM

static constexpr int A_CHUNKS  = TM * (TK / 16);     // 1024
static constexpr int B_CHUNKS  = TNT * (TK / 16);    // 512
static constexpr int B2_CHUNKS = B2_TILE_BYTES / 16; // 512
static constexpr int TOT_CHUNKS = A_CHUNKS + B_CHUNKS + B2_CHUNKS; // 2048 = 4*512

static constexpr int NTHREADS = 512;   // 8 tensor warps + 8 dp4a warps

// Scratch (__device__ globals: the allowed allocation-free path)
__device__ int8_t  g_xq[(size_t)N_TOK * KDIM];    // quantized activations [N,K]
__device__ int8_t  g_wb[(size_t)MDIM * KDIM];     // weight transposed [M,K]
__device__ uint8_t g_wb2[(size_t)TILES_M * (KDIM / 4) * TND * 4];  // dp4a B packed

// ============================================================================
// PTX helpers
// ============================================================================
__device__ __forceinline__ uint32_t smem_to_u32(const void* p) {
    uint32_t a;
    asm("{ .reg .u64 t; cvta.to.shared.u64 t, %1; cvt.u32.u64 %0, t; }" : "=r"(a) : "l"(p));
    return a;
}
__device__ __forceinline__ void cp_async16(uint32_t dst, const void* src) {
    asm volatile("cp.async.cg.shared.global [%0], [%1], 16;" :: "r"(dst), "l"(src));
}
#define CP_COMMIT() asm volatile("cp.async.commit_group;" ::: "memory")
#define CP_WAIT1()  asm volatile("cp.async.wait_group 1;" ::: "memory")

__device__ __forceinline__ void ldmatrix_x4(uint32_t* r, uint32_t addr) {
    asm volatile("ldmatrix.sync.aligned.m8n8.x4.shared.b16 {%0,%1,%2,%3}, [%4];"
                 : "=r"(r[0]), "=r"(r[1]), "=r"(r[2]), "=r"(r[3]) : "r"(addr));
}
__device__ __forceinline__ void mma_s8(int* c, const uint32_t* a, const uint32_t* b) {
    asm volatile(
        "mma.sync.aligned.m16n8k32.row.col.s32.s8.s8.s32 "
        "{%0,%1,%2,%3}, {%4,%5,%6,%7}, {%8,%9}, {%0,%1,%2,%3};"
        : "+r"(c[0]), "+r"(c[1]), "+r"(c[2]), "+r"(c[3])
        : "r"(a[0]), "r"(a[1]), "r"(a[2]), "r"(a[3]), "r"(b[0]), "r"(b[1]));
}
__device__ __forceinline__ void lds128(uint32_t* r, uint32_t addr) {
    asm volatile("ld.shared.v4.u32 {%0,%1,%2,%3}, [%4];"
                 : "=r"(r[0]), "=r"(r[1]), "=r"(r[2]), "=r"(r[3]) : "r"(addr));
}
__device__ __forceinline__ uint32_t lds32(uint32_t addr) {
    uint32_t r;
    asm volatile("ld.shared.u32 %0, [%1];" : "=r"(r) : "r"(addr));
    return r;
}

// ============================================================================
// Kernel 1: quantize x -> int8. q = clamp(rne(x*50), -128, 127). MLP=8.
// ============================================================================
__global__ __launch_bounds__(256) void quant_kernel(const float* __restrict__ x) {
    const int base = blockIdx.x * 2048 + threadIdx.x;
    const float4* xv = reinterpret_cast<const float4*>(x);
    float4 v[8];
#pragma unroll
    for (int k = 0; k < 8; ++k) v[k] = xv[base + k * 256];
#pragma unroll
    for (int k = 0; k < 8; ++k) {
        int q0 = min(max(__float2int_rn(v[k].x * 50.0f), -128), 127);
        int q1 = min(max(__float2int_rn(v[k].y * 50.0f), -128), 127);
        int q2 = min(max(__float2int_rn(v[k].z * 50.0f), -128), 127);
        int q3 = min(max(__float2int_rn(v[k].w * 50.0f), -128), 127);
        uint32_t lo = __byte_perm((uint32_t)q0, (uint32_t)q1, 0x4040);
        uint32_t hi = __byte_perm((uint32_t)q2, (uint32_t)q3, 0x4040);
        reinterpret_cast<uint32_t*>(g_xq)[base + k * 256] = __byte_perm(lo, hi, 0x5410);
    }
}

// ============================================================================
// dtype detection helper (harness promotes int8 tensors to int32/fp32)
// ============================================================================
__device__ __forceinline__ int detect_mode(const void* w) {
    const int32_t* wi = (const int32_t*)w;
    const float*   wf = (const float*)w;
    bool ok32 = true, okf = true;
    for (int i = threadIdx.x; i < 1024; i += blockDim.x) {
        int32_t a = wi[i];
        ok32 &= (a >= -128 && a <= 127);
        float f = wf[i];
        okf  &= (f == rintf(f) && f >= -128.f && f <= 127.f);
    }
    ok32 = __syncthreads_and(ok32);
    okf  = __syncthreads_and(okf);
    return ok32 ? 1 : (okf ? 2 : 0);
}
__device__ __forceinline__ int8_t read_w(const void* w, size_t idx, int mode) {
    if (mode == 1) return (int8_t)((const int32_t*)w)[idx];
    if (mode == 2) return (int8_t)(int)((const float*)w)[idx];
    return ((const int8_t*)w)[idx];
}

// ============================================================================
// Kernel 2: transpose weight [K,M] -> [M,K] int8 (tensor-warp operand)
// ============================================================================
__global__ __launch_bounds__(256) void wtrans_kernel(const void* __restrict__ wsrc) {
    __shared__ int8_t t[32][33];
    const int mode = detect_mode(wsrc);
    const int kb = blockIdx.x * 32, mb = blockIdx.y * 32;
    const int tx = threadIdx.x & 31, ty = threadIdx.x >> 5;
#pragma unroll
    for (int i = 0; i < 4; ++i) {
        int r = ty + i * 8;
        t[r][tx] = read_w(wsrc, (size_t)(kb + r) * MDIM + mb + tx, mode);
    }
    __syncthreads();
#pragma unroll
    for (int i = 0; i < 4; ++i) {
        int r = ty + i * 8;
        g_wb[(size_t)(mb + r) * KDIM + kb + tx] = t[tx][r];
    }
}

// ============================================================================
// Kernel 2b: pack dp4a B: g_wb2[mblk][kc][col] = w[4kc..4kc+3][mblk*128+64+col]
// ============================================================================
__global__ __launch_bounds__(256) void wpack2_kernel(const void* __restrict__ wsrc) {
    const int mode = detect_mode(wsrc);
    const int t = blockIdx.x * 256 + threadIdx.x;     // over 6*192*64 = 73728
    if (t >= TILES_M * (KDIM / 4) * TND) return;
    const int mb  = t / ((KDIM / 4) * TND);
    const int rem = t - mb * ((KDIM / 4) * TND);
    const int kc  = rem / TND;
    const int col = rem - kc * TND;
    const int m = mb * TN + TNT + col;
    uint32_t p = 0;
#pragma unroll
    for (int j = 0; j < 4; ++j) {
        int8_t b = read_w(wsrc, (size_t)(kc * 4 + j) * MDIM + m, mode);
        p |= (uint32_t)(uint8_t)b << (j * 8);
    }
    reinterpret_cast<uint32_t*>(g_wb2)[t] = p;
}

// ============================================================================
// Kernel 3: hybrid GEMM. CTA tile 128x128, 512 threads, 2 CTA/SM:
//   warps 0-7 : mma path, cols [0,64): warp = 32 rows x 32 cols
//   warps 8-15: dp4a path, cols [64,128): warp = (32-row slab, 32-col half)
// TK=128, 3-stage ring. Register-slimmed for the 64-reg cap at occupancy 2.
// ============================================================================
__global__ __launch_bounds__(NTHREADS, 2)
void gemm_kernel(const float* __restrict__ bias, float* __restrict__ out) {
    extern __shared__ char smem[];
    const uint32_t sbase = smem_to_u32(smem);
    const int tid  = threadIdx.x;
    const int lane = tid & 31;
    const int warp = tid >> 5;
    const int m0 = blockIdx.x * TN;    // 6 column tiles
    const int n0 = blockIdx.y * TM;    // 256 token tiles
    const int mblk = blockIdx.x;

    auto load_stage = [&](int s) {
        const int buf = s % STAGES;
        const uint32_t sa  = sbase + buf * STAGE_BYTES;
        const uint32_t sb  = sa + A_TILE_BYTES;
        const uint32_t sb2 = sb + B_TILE_BYTES;
        const int k0 = s * TK;
#pragma unroll
        for (int it = 0; it < 4; ++it) {
            int g = tid + it * NTHREADS;          // 0..2047
            if (g < A_CHUNKS) {
                int row = g >> 3, c = g & 7;      // 8 chunks per 128B row
                cp_async16(sa + row * ROWPAD + c * 16,
                           g_xq + (size_t)(n0 + row) * KDIM + k0 + c * 16);
            } else if (g < A_CHUNKS + B_CHUNKS) {
                int h = g - A_CHUNKS;             // 0..511
                int row = h >> 3, c = h & 7;
                cp_async16(sb + row * ROWPAD + c * 16,
                           g_wb + (size_t)(m0 + row) * KDIM + k0 + c * 16);
            } else {
                int h = g - A_CHUNKS - B_CHUNKS;  // 0..511
                cp_async16(sb2 + h * 16,
                           g_wb2 + (size_t)mblk * (KDIM / 4) * TND * 4
                                 + (size_t)(k0 / 4) * TND * 4 + h * 16);
            }
        }
    };

    load_stage(0); CP_COMMIT();
    load_stage(1); CP_COMMIT();

    const float eff = (float)(0.02 * 0.01);

    if (warp < 8) {
        // ================== tensor path: 64 cols ==================
        const int wm = warp >> 1;          // 0..3 : 32-token slab
        const int wn = warp & 1;           // 0..1 : 32-col half
        int acc[2][4][4];
#pragma unroll
        for (int i = 0; i < 2; ++i)
#pragma unroll
            for (int j = 0; j < 4; ++j)
#pragma unroll
                for (int k = 0; k < 4; ++k) acc[i][j][k] = 0;

        const int a_row = (lane & 7) + ((lane >> 3) & 1) * 8;
        const int a_kb  = (lane >> 4) * 16;
        const int b_row = lane & 7;
        const int b_grp = (lane >> 4) & 1;
        const int b_kb  = ((lane >> 3) & 1) * 16;

        for (int s = 0; s < KSTEPS; ++s) {
            CP_WAIT1();
            __syncthreads();
            if (s + 2 < KSTEPS) load_stage(s + 2);
            CP_COMMIT();
            const int buf = s % STAGES;
            const uint32_t sa = sbase + buf * STAGE_BYTES;
            const uint32_t sb = sa + A_TILE_BYTES;
#pragma unroll
            for (int kk = 0; kk < 4; ++kk) {   // four k32 steps per 128B stage
                uint32_t afrag[2][4], bfrag[4][2];
                const uint32_t abase =
                    sa + (uint32_t)(wm * 32 + a_row) * ROWPAD + kk * 32 + a_kb;
#pragma unroll
                for (int mf = 0; mf < 2; ++mf)
                    ldmatrix_x4(afrag[mf], abase + (uint32_t)mf * 16 * ROWPAD);
                const uint32_t bbase =
                    sb + (uint32_t)(wn * 32 + b_grp * 8 + b_row) * ROWPAD + kk * 32 + b_kb;
#pragma unroll
                for (int np = 0; np < 2; ++np) {
                    uint32_t r[4];
                    ldmatrix_x4(r, bbase + (uint32_t)np * 16 * ROWPAD);
                    bfrag[np * 2 + 0][0] = r[0];
                    bfrag[np * 2 + 0][1] = r[1];
                    bfrag[np * 2 + 1][0] = r[2];
                    bfrag[np * 2 + 1][1] = r[3];
                }
#pragma unroll
                for (int mf = 0; mf < 2; ++mf)
#pragma unroll
                    for (int nf = 0; nf < 4; ++nf)
                        mma_s8(acc[mf][nf], afrag[mf], bfrag[nf]);
            }
        }
        // epilogue (bias loaded inline to keep live regs low in mainloop)
#pragma unroll
        for (int mf = 0; mf < 2; ++mf) {
            const int row_lo = n0 + wm * 32 + mf * 16 + (lane >> 2);
            float* p_lo = out + (size_t)row_lo * MDIM;
            float* p_hi = p_lo + 8 * MDIM;
#pragma unroll
            for (int nf = 0; nf < 4; ++nf) {
                const int col = m0 + wn * 32 + nf * 8 + 2 * (lane & 3);
                const float b0 = __ldg(bias + col);
                const float b1 = __ldg(bias + col + 1);
                float2 lo, hi;
                lo.x = (float)acc[mf][nf][0] * eff + b0;
                lo.y = (float)acc[mf][nf][1] * eff + b1;
                hi.x = (float)acc[mf][nf][2] * eff + b0;
                hi.y = (float)acc[mf][nf][3] * eff + b1;
                *reinterpret_cast<float2*>(p_lo + col) = lo;
                *reinterpret_cast<float2*>(p_hi + col) = hi;
            }
        }
    } else {
        // ================== dp4a path: 64 cols on the IMAD pipe ==================
        const int w  = warp - 8;          // 0..7
        const int rs = w & 3;             // 32-row slab
        const int ch = w >> 2;            // 0..1 : 32-col half
        const int rg = lane >> 2;         // 0..7 : 4-row group
        const int cg = lane & 3;          // 0..3 : 8-col group
        int dacc[4][8];
#pragma unroll
        for (int i = 0; i < 4; ++i)
#pragma unroll
            for (int j = 0; j < 8; ++j) dacc[i][j] = 0;

        const uint32_t arow0 = (uint32_t)(rs * 32 + rg * 4);
        const uint32_t bcol0 = (uint32_t)(ch * 32 + cg * 8);

        for (int s = 0; s < KSTEPS; ++s) {
            CP_WAIT1();
            __syncthreads();
            if (s + 2 < KSTEPS) load_stage(s + 2);
            CP_COMMIT();
            const int buf = s % STAGES;
            const uint32_t sa  = sbase + buf * STAGE_BYTES;
            const uint32_t sb2 = sa + A_TILE_BYTES + B_TILE_BYTES;
#pragma unroll
            for (int kk = 0; kk < 4; ++kk) {
#pragma unroll
                for (int h = 0; h < 2; ++h) {      // k16 halves
                    const uint32_t abase = sa + arow0 * ROWPAD + kk * 32 + h * 16;
#pragma unroll
                    for (int c = 0; c < 4; ++c) {  // 4 k-chunks in this half
                        // b operands: 8 cols x 1 chunk (two lds128)
                        const uint32_t boff =
                            sb2 + (uint32_t)(((kk * 8 + h * 4 + c) * TND + bcol0) * 4);
                        uint32_t b[8];
                        lds128(b, boff);
                        lds128(b + 4, boff + 16);
                        // a operands: 4 rows x 1 chunk via lds32 (low reg count)
                        uint32_t a0 = lds32(abase + 0 * ROWPAD + c * 4);
                        uint32_t a1 = lds32(abase + 1 * ROWPAD + c * 4);
                        uint32_t a2 = lds32(abase + 2 * ROWPAD + c * 4);
                        uint32_t a3 = lds32(abase + 3 * ROWPAD + c * 4);
#pragma unroll
                        for (int j = 0; j < 8; ++j) {
                            dacc[0][j] = __dp4a((int)a0, (int)b[j], dacc[0][j]);
                            dacc[1][j] = __dp4a((int)a1, (int)b[j], dacc[1][j]);
                            dacc[2][j] = __dp4a((int)a2, (int)b[j], dacc[2][j]);
                            dacc[3][j] = __dp4a((int)a3, (int)b[j], dacc[3][j]);
                        }
                    }
                }
            }
        }
        // epilogue
        const int bcol = m0 + TNT + (int)bcol0;
#pragma unroll
        for (int i = 0; i < 4; ++i) {
            const int row = n0 + (int)arow0 + i;
            float* p = out + (size_t)row * MDIM + bcol;
            float4 v0, v1;
            v0.x = (float)dacc[i][0] * eff + __ldg(bias + bcol + 0);
            v0.y = (float)dacc[i][1] * eff + __ldg(bias + bcol + 1);
            v0.z = (float)dacc[i][2] * eff + __ldg(bias + bcol + 2);
            v0.w = (float)dacc[i][3] * eff + __ldg(bias + bcol + 3);
            v1.x = (float)dacc[i][4] * eff + __ldg(bias + bcol + 4);
            v1.y = (float)dacc[i][5] * eff + __ldg(bias + bcol + 5);
            v1.z = (float)dacc[i][6] * eff + __ldg(bias + bcol + 6);
            v1.w = (float)dacc[i][7] * eff + __ldg(bias + bcol + 7);
            *reinterpret_cast<float4*>(p) = v0;
            *reinterpret_cast<float4*>(p + 4) = v1;
        }
    }
}

// ============================================================================
// Launch
// ============================================================================
extern "C" void kernel_launch(void* const* d_in, const int* in_sizes, int n_in,
                              void* d_out, int out_size) {
    const float* x    = (const float*)d_in[0];
    const void*  wt   = d_in[1];
    const float* bias = (const float*)d_in[2];
    float*       out  = (float*)d_out;

    cudaFuncSetAttribute(gemm_kernel, cudaFuncAttributeMaxDynamicSharedMemorySize,
                         SMEM_ALLOC);

    {
        int nblk = (N_TOK * KDIM) / 4 / 2048;   // 3072 blocks
        quant_kernel<<<nblk, 256>>>(x);
    }
    {
        dim3 grid(KDIM / 32, MDIM / 32);
        wtrans_kernel<<<grid, 256>>>(wt);
    }
    {
        int n = TILES_M * (KDIM / 4) * TND;     // 73728
        wpack2_kernel<<<(n + 255) / 256, 256>>>(wt);
    }
    {
        dim3 grid(MDIM / TN, N_TOK / TM);       // (6, 256) = 1536 tiles
        gemm_kernel<<<grid, NTHREADS, SMEM_ALLOC>>>(bias, out);
    }
    (void)in_sizes; (void)n_in; (void)out_size;
}

// round 16
// speedup vs baseline: 1.1768x; 1.0224x over previous
#include <cuda_runtime.h>
#include <cuda_bf16.h>
#include <cstdint>

// ============================================================================
// x(8,4096,768) fp32 -> int8 quant -> GEMM vs weight_t(768,768) int8 (promoted
// to int32/fp32 by harness; detected) -> int32 acc * 2e-4 + bias -> fp32 out.
// Legacy mma.sync path (compute_103 baseline PTX; tcgen05 unavailable).
// R16: the GEMM is ISSUE-slot bound (57% issue, both pipes <65%). Cut dp4a
//      operand-fetch issues: a via lds64 pairs (8/kk-h), b via lds128
//      (~150 issues per 512 MACs vs 176). Merge the 3 prep kernels into one
//      launch (partitioned grid). Tile/warp layout = R15 (2 CTA/SM, 8+8).
// ============================================================================
static constexpr int N_TOK = 32768;
static constexpr int KDIM  = 768;
static constexpr int MDIM  = 768;

static constexpr int TM = 128;      // token tile
static constexpr int TNT = 64;      // tensor-warp cols
static constexpr int TND = 64;      // dp4a-warp cols
static constexpr int TN  = TNT + TND;              // 128
static constexpr int TK = 128;      // K bytes per stage
static constexpr int STAGES = 3;
static constexpr int KSTEPS = KDIM / TK;           // 6
static constexpr int TILES_M = MDIM / TN;          // 6
static constexpr int ROWPAD = 144;  // 128B data + 16B pad: conflict-free
static constexpr int A_TILE_BYTES  = TM * ROWPAD;            // 18432
static constexpr int B_TILE_BYTES  = TNT * ROWPAD;           // 9216
static constexpr int B2_TILE_BYTES = (TK / 4) * TND * 4;     // 8192
static constexpr int STAGE_BYTES = A_TILE_BYTES + B_TILE_BYTES + B2_TILE_BYTES; // 35840
static constexpr int SMEM_ALLOC  = STAGES * STAGE_BYTES;     // 107520 -> 2 CTA/SM

static constexpr int A_CHUNKS  = TM * (TK / 16);     // 1024
static constexpr int B_CHUNKS  = TNT * (TK / 16);    // 512
static constexpr int B2_CHUNKS = B2_TILE_BYTES / 16; // 512
static constexpr int TOT_CHUNKS = A_CHUNKS + B_CHUNKS + B2_CHUNKS; // 2048 = 4*512

static constexpr int NTHREADS = 512;   // 8 tensor warps + 8 dp4a warps

// Merged prep kernel grid partition
static constexpr int QUANT_BLOCKS  = (N_TOK * KDIM) / 4 / 2048;          // 3072
static constexpr int WTRANS_BLOCKS = (KDIM / 32) * (MDIM / 32);          // 576
static constexpr int WPACK_BLOCKS  = (TILES_M * (KDIM / 4) * TND) / 256; // 288
static constexpr int PREP_BLOCKS   = QUANT_BLOCKS + WTRANS_BLOCKS + WPACK_BLOCKS;

// Scratch (__device__ globals: the allowed allocation-free path)
__device__ int8_t  g_xq[(size_t)N_TOK * KDIM];    // quantized activations [N,K]
__device__ int8_t  g_wb[(size_t)MDIM * KDIM];     // weight transposed [M,K]
__device__ uint8_t g_wb2[(size_t)TILES_M * (KDIM / 4) * TND * 4];  // dp4a B packed

// ============================================================================
// PTX helpers
// ============================================================================
__device__ __forceinline__ uint32_t smem_to_u32(const void* p) {
    uint32_t a;
    asm("{ .reg .u64 t; cvta.to.shared.u64 t, %1; cvt.u32.u64 %0, t; }" : "=r"(a) : "l"(p));
    return a;
}
__device__ __forceinline__ void cp_async16(uint32_t dst, const void* src) {
    asm volatile("cp.async.cg.shared.global [%0], [%1], 16;" :: "r"(dst), "l"(src));
}
#define CP_COMMIT() asm volatile("cp.async.commit_group;" ::: "memory")
#define CP_WAIT1()  asm volatile("cp.async.wait_group 1;" ::: "memory")

__device__ __forceinline__ void ldmatrix_x4(uint32_t* r, uint32_t addr) {
    asm volatile("ldmatrix.sync.aligned.m8n8.x4.shared.b16 {%0,%1,%2,%3}, [%4];"
                 : "=r"(r[0]), "=r"(r[1]), "=r"(r[2]), "=r"(r[3]) : "r"(addr));
}
__device__ __forceinline__ void mma_s8(int* c, const uint32_t* a, const uint32_t* b) {
    asm volatile(
        "mma.sync.aligned.m16n8k32.row.col.s32.s8.s8.s32 "
        "{%0,%1,%2,%3}, {%4,%5,%6,%7}, {%8,%9}, {%0,%1,%2,%3};"
        : "+r"(c[0]), "+r"(c[1]), "+r"(c[2]), "+r"(c[3])
        : "r"(a[0]), "r"(a[1]), "r"(a[2]), "r"(a[3]), "r"(b[0]), "r"(b[1]));
}
__device__ __forceinline__ void lds128(uint32_t* r, uint32_t addr) {
    asm volatile("ld.shared.v4.u32 {%0,%1,%2,%3}, [%4];"
                 : "=r"(r[0]), "=r"(r[1]), "=r"(r[2]), "=r"(r[3]) : "r"(addr));
}
__device__ __forceinline__ void lds64(uint32_t& r0, uint32_t& r1, uint32_t addr) {
    asm volatile("ld.shared.v2.u32 {%0,%1}, [%2];"
                 : "=r"(r0), "=r"(r1) : "r"(addr));
}

// ============================================================================
// dtype detection helper (harness promotes int8 tensors to int32/fp32)
// ============================================================================
__device__ __forceinline__ int detect_mode(const void* w) {
    const int32_t* wi = (const int32_t*)w;
    const float*   wf = (const float*)w;
    bool ok32 = true, okf = true;
    for (int i = threadIdx.x; i < 1024; i += blockDim.x) {
        int32_t a = wi[i];
        ok32 &= (a >= -128 && a <= 127);
        float f = wf[i];
        okf  &= (f == rintf(f) && f >= -128.f && f <= 127.f);
    }
    ok32 = __syncthreads_and(ok32);
    okf  = __syncthreads_and(okf);
    return ok32 ? 1 : (okf ? 2 : 0);
}
__device__ __forceinline__ int8_t read_w(const void* w, size_t idx, int mode) {
    if (mode == 1) return (int8_t)((const int32_t*)w)[idx];
    if (mode == 2) return (int8_t)(int)((const float*)w)[idx];
    return ((const int8_t*)w)[idx];
}

// ============================================================================
// Merged prep kernel: quant (blocks [0,3072)), wtrans ([3072,3648)),
// wpack2 ([3648,3936)). One launch; DRAM-bound quant overlaps L2-bound prep.
// ============================================================================
__global__ __launch_bounds__(256) void prep_kernel(const float* __restrict__ x,
                                                   const void* __restrict__ wsrc) {
    __shared__ int8_t t[32][33];
    const int bid = blockIdx.x;
    if (bid < QUANT_BLOCKS) {
        // ---- quantize: q = clamp(rne(x*50), -128, 127), MLP=8
        const int base = bid * 2048 + threadIdx.x;
        const float4* xv = reinterpret_cast<const float4*>(x);
        float4 v[8];
#pragma unroll
        for (int k = 0; k < 8; ++k) v[k] = xv[base + k * 256];
#pragma unroll
        for (int k = 0; k < 8; ++k) {
            int q0 = min(max(__float2int_rn(v[k].x * 50.0f), -128), 127);
            int q1 = min(max(__float2int_rn(v[k].y * 50.0f), -128), 127);
            int q2 = min(max(__float2int_rn(v[k].z * 50.0f), -128), 127);
            int q3 = min(max(__float2int_rn(v[k].w * 50.0f), -128), 127);
            uint32_t lo = __byte_perm((uint32_t)q0, (uint32_t)q1, 0x4040);
            uint32_t hi = __byte_perm((uint32_t)q2, (uint32_t)q3, 0x4040);
            reinterpret_cast<uint32_t*>(g_xq)[base + k * 256] =
                __byte_perm(lo, hi, 0x5410);
        }
    } else if (bid < QUANT_BLOCKS + WTRANS_BLOCKS) {
        // ---- transpose weight [K,M] -> [M,K]
        const int mode = detect_mode(wsrc);
        const int b2 = bid - QUANT_BLOCKS;
        const int kb = (b2 % (KDIM / 32)) * 32;
        const int mb = (b2 / (KDIM / 32)) * 32;
        const int tx = threadIdx.x & 31, ty = threadIdx.x >> 5;
#pragma unroll
        for (int i = 0; i < 4; ++i) {
            int r = ty + i * 8;
            t[r][tx] = read_w(wsrc, (size_t)(kb + r) * MDIM + mb + tx, mode);
        }
        __syncthreads();
#pragma unroll
        for (int i = 0; i < 4; ++i) {
            int r = ty + i * 8;
            g_wb[(size_t)(mb + r) * KDIM + kb + tx] = t[tx][r];
        }
    } else {
        // ---- pack dp4a B: g_wb2[mblk][kc][col] = w[4kc..4kc+3][mblk*128+64+col]
        const int mode = detect_mode(wsrc);
        const int idx = (bid - QUANT_BLOCKS - WTRANS_BLOCKS) * 256 + threadIdx.x;
        const int mb  = idx / ((KDIM / 4) * TND);
        const int rem = idx - mb * ((KDIM / 4) * TND);
        const int kc  = rem / TND;
        const int col = rem - kc * TND;
        const int m = mb * TN + TNT + col;
        uint32_t p = 0;
#pragma unroll
        for (int j = 0; j < 4; ++j) {
            int8_t b = read_w(wsrc, (size_t)(kc * 4 + j) * MDIM + m, mode);
            p |= (uint32_t)(uint8_t)b << (j * 8);
        }
        reinterpret_cast<uint32_t*>(g_wb2)[idx] = p;
    }
}

// ============================================================================
// Hybrid GEMM. CTA tile 128x128, 512 threads, 2 CTA/SM:
//   warps 0-7 : mma path, cols [0,64): warp = 32 rows x 32 cols
//   warps 8-15: dp4a path, cols [64,128): warp = (32-row slab, 32-col half)
// TK=128, 3-stage ring. dp4a operands: a via lds64 pairs, b via lds128.
// ============================================================================
__global__ __launch_bounds__(NTHREADS, 2)
void gemm_kernel(const float* __restrict__ bias, float* __restrict__ out) {
    extern __shared__ char smem[];
    const uint32_t sbase = smem_to_u32(smem);
    const int tid  = threadIdx.x;
    const int lane = tid & 31;
    const int warp = tid >> 5;
    const int m0 = blockIdx.x * TN;    // 6 column tiles
    const int n0 = blockIdx.y * TM;    // 256 token tiles
    const int mblk = blockIdx.x;

    auto load_stage = [&](int s) {
        const int buf = s % STAGES;
        const uint32_t sa  = sbase + buf * STAGE_BYTES;
        const uint32_t sb  = sa + A_TILE_BYTES;
        const uint32_t sb2 = sb + B_TILE_BYTES;
        const int k0 = s * TK;
#pragma unroll
        for (int it = 0; it < 4; ++it) {
            int g = tid + it * NTHREADS;          // 0..2047
            if (g < A_CHUNKS) {
                int row = g >> 3, c = g & 7;      // 8 chunks per 128B row
                cp_async16(sa + row * ROWPAD + c * 16,
                           g_xq + (size_t)(n0 + row) * KDIM + k0 + c * 16);
            } else if (g < A_CHUNKS + B_CHUNKS) {
                int h = g - A_CHUNKS;             // 0..511
                int row = h >> 3, c = h & 7;
                cp_async16(sb + row * ROWPAD + c * 16,
                           g_wb + (size_t)(m0 + row) * KDIM + k0 + c * 16);
            } else {
                int h = g - A_CHUNKS - B_CHUNKS;  // 0..511
                cp_async16(sb2 + h * 16,
                           g_wb2 + (size_t)mblk * (KDIM / 4) * TND * 4
                                 + (size_t)(k0 / 4) * TND * 4 + h * 16);
            }
        }
    };

    load_stage(0); CP_COMMIT();
    load_stage(1); CP_COMMIT();

    const float eff = (float)(0.02 * 0.01);

    if (warp < 8) {
        // ================== tensor path: 64 cols ==================
        const int wm = warp >> 1;          // 0..3 : 32-token slab
        const int wn = warp & 1;           // 0..1 : 32-col half
        int acc[2][4][4];
#pragma unroll
        for (int i = 0; i < 2; ++i)
#pragma unroll
            for (int j = 0; j < 4; ++j)
#pragma unroll
                for (int k = 0; k < 4; ++k) acc[i][j][k] = 0;

        const int a_row = (lane & 7) + ((lane >> 3) & 1) * 8;
        const int a_kb  = (lane >> 4) * 16;
        const int b_row = lane & 7;
        const int b_grp = (lane >> 4) & 1;
        const int b_kb  = ((lane >> 3) & 1) * 16;

        for (int s = 0; s < KSTEPS; ++s) {
            CP_WAIT1();
            __syncthreads();
            if (s + 2 < KSTEPS) load_stage(s + 2);
            CP_COMMIT();
            const int buf = s % STAGES;
            const uint32_t sa = sbase + buf * STAGE_BYTES;
            const uint32_t sb = sa + A_TILE_BYTES;
#pragma unroll
            for (int kk = 0; kk < 4; ++kk) {   // four k32 steps per 128B stage
                uint32_t afrag[2][4], bfrag[4][2];
                const uint32_t abase =
                    sa + (uint32_t)(wm * 32 + a_row) * ROWPAD + kk * 32 + a_kb;
#pragma unroll
                for (int mf = 0; mf < 2; ++mf)
                    ldmatrix_x4(afrag[mf], abase + (uint32_t)mf * 16 * ROWPAD);
                const uint32_t bbase =
                    sb + (uint32_t)(wn * 32 + b_grp * 8 + b_row) * ROWPAD + kk * 32 + b_kb;
#pragma unroll
                for (int np = 0; np < 2; ++np) {
                    uint32_t r[4];
                    ldmatrix_x4(r, bbase + (uint32_t)np * 16 * ROWPAD);
                    bfrag[np * 2 + 0][0] = r[0];
                    bfrag[np * 2 + 0][1] = r[1];
                    bfrag[np * 2 + 1][0] = r[2];
                    bfrag[np * 2 + 1][1] = r[3];
                }
#pragma unroll
                for (int mf = 0; mf < 2; ++mf)
#pragma unroll
                    for (int nf = 0; nf < 4; ++nf)
                        mma_s8(acc[mf][nf], afrag[mf], bfrag[nf]);
            }
        }
        // epilogue
#pragma unroll
        for (int mf = 0; mf < 2; ++mf) {
            const int row_lo = n0 + wm * 32 + mf * 16 + (lane >> 2);
            float* p_lo = out + (size_t)row_lo * MDIM;
            float* p_hi = p_lo + 8 * MDIM;
#pragma unroll
            for (int nf = 0; nf < 4; ++nf) {
                const int col = m0 + wn * 32 + nf * 8 + 2 * (lane & 3);
                const float b0 = __ldg(bias + col);
                const float b1 = __ldg(bias + col + 1);
                float2 lo, hi;
                lo.x = (float)acc[mf][nf][0] * eff + b0;
                lo.y = (float)acc[mf][nf][1] * eff + b1;
                hi.x = (float)acc[mf][nf][2] * eff + b0;
                hi.y = (float)acc[mf][nf][3] * eff + b1;
                *reinterpret_cast<float2*>(p_lo + col) = lo;
                *reinterpret_cast<float2*>(p_hi + col) = hi;
            }
        }
    } else {
        // ================== dp4a path: 64 cols on the IMAD pipe ==================
        const int w  = warp - 8;          // 0..7
        const int rs = w & 3;             // 32-row slab
        const int ch = w >> 2;            // 0..1 : 32-col half
        const int rg = lane >> 2;         // 0..7 : 4-row group
        const int cg = lane & 3;          // 0..3 : 8-col group
        int dacc[4][8];
#pragma unroll
        for (int i = 0; i < 4; ++i)
#pragma unroll
            for (int j = 0; j < 8; ++j) dacc[i][j] = 0;

        const uint32_t arow0 = (uint32_t)(rs * 32 + rg * 4);
        const uint32_t bcol0 = (uint32_t)(ch * 32 + cg * 8);

        for (int s = 0; s < KSTEPS; ++s) {
            CP_WAIT1();
            __syncthreads();
            if (s + 2 < KSTEPS) load_stage(s + 2);
            CP_COMMIT();
            const int buf = s % STAGES;
            const uint32_t sa  = sbase + buf * STAGE_BYTES;
            const uint32_t sb2 = sa + A_TILE_BYTES + B_TILE_BYTES;
#pragma unroll
            for (int kk = 0; kk < 4; ++kk) {
#pragma unroll
                for (int h = 0; h < 2; ++h) {      // k16 halves
                    const uint32_t abase = sa + arow0 * ROWPAD + kk * 32 + h * 16;
#pragma unroll
                    for (int cp = 0; cp < 2; ++cp) {   // c-pairs
                        // a: 4 rows x 2 chunks via lds64 (8 live regs)
                        uint32_t a0l, a0h, a1l, a1h, a2l, a2h, a3l, a3h;
                        lds64(a0l, a0h, abase + 0 * ROWPAD + cp * 8);
                        lds64(a1l, a1h, abase + 1 * ROWPAD + cp * 8);
                        lds64(a2l, a2h, abase + 2 * ROWPAD + cp * 8);
                        lds64(a3l, a3h, abase + 3 * ROWPAD + cp * 8);
#pragma unroll
                        for (int c2 = 0; c2 < 2; ++c2) {
                            const int c = cp * 2 + c2;
                            const uint32_t boff =
                                sb2 + (uint32_t)(((kk * 8 + h * 4 + c) * TND + bcol0) * 4);
                            uint32_t b[8];
                            lds128(b, boff);
                            lds128(b + 4, boff + 16);
                            const uint32_t ar0 = c2 ? a0h : a0l;
                            const uint32_t ar1 = c2 ? a1h : a1l;
                            const uint32_t ar2 = c2 ? a2h : a2l;
                            const uint32_t ar3 = c2 ? a3h : a3l;
#pragma unroll
                            for (int j = 0; j < 8; ++j) {
                                dacc[0][j] = __dp4a((int)ar0, (int)b[j], dacc[0][j]);
                                dacc[1][j] = __dp4a((int)ar1, (int)b[j], dacc[1][j]);
                                dacc[2][j] = __dp4a((int)ar2, (int)b[j], dacc[2][j]);
                                dacc[3][j] = __dp4a((int)ar3, (int)b[j], dacc[3][j]);
                            }
                        }
                    }
                }
            }
        }
        // epilogue
        const int bcol = m0 + TNT + (int)bcol0;
#pragma unroll
        for (int i = 0; i < 4; ++i) {
            const int row = n0 + (int)arow0 + i;
            float* p = out + (size_t)row * MDIM + bcol;
            float4 v0, v1;
            v0.x = (float)dacc[i][0] * eff + __ldg(bias + bcol + 0);
            v0.y = (float)dacc[i][1] * eff + __ldg(bias + bcol + 1);
            v0.z = (float)dacc[i][2] * eff + __ldg(bias + bcol + 2);
            v0.w = (float)dacc[i][3] * eff + __ldg(bias + bcol + 3);
            v1.x = (float)dacc[i][4] * eff + __ldg(bias + bcol + 4);
            v1.y = (float)dacc[i][5] * eff + __ldg(bias + bcol + 5);
            v1.z = (float)dacc[i][6] * eff + __ldg(bias + bcol + 6);
            v1.w = (float)dacc[i][7] * eff + __ldg(bias + bcol + 7);
            *reinterpret_cast<float4*>(p) = v0;
            *reinterpret_cast<float4*>(p + 4) = v1;
        }
    }
}

// ============================================================================
// Launch
// ============================================================================
extern "C" void kernel_launch(void* const* d_in, const int* in_sizes, int n_in,
                              void* d_out, int out_size) {
    const float* x    = (const float*)d_in[0];
    const void*  wt   = d_in[1];
    const float* bias = (const float*)d_in[2];
    float*       out  = (float*)d_out;

    cudaFuncSetAttribute(gemm_kernel, cudaFuncAttributeMaxDynamicSharedMemorySize,
                         SMEM_ALLOC);

    prep_kernel<<<PREP_BLOCKS, 256>>>(x, wt);
    {
        dim3 grid(MDIM / TN, N_TOK / TM);       // (6, 256) = 1536 tiles
        gemm_kernel<<<grid, NTHREADS, SMEM_ALLOC>>>(bias, out);
    }
    (void)in_sizes; (void)n_in; (void)out_size;
}